// round 1
// baseline (speedup 1.0000x reference)
#include <cuda_runtime.h>
#include <cuda_bf16.h>

// Problem constants
#define B_      32
#define C_      256
#define HW_     1024           // H*W = 32*32
#define NTOK    32768          // B*H*W
#define KCODES  1024
#define BETA    0.25f

// Output layout (concatenated float32): u, z_train, vq_loss, indices
#define SZ_U    8388608        // 32*256*32*32
#define OFF_U   0
#define OFF_ZT  8388608
#define OFF_LOSS 16777216
#define OFF_IDX  16777217

// GEMM tiling
#define BT 64     // tokens per block
#define KT 64     // codes per code-tile
#define CK 32     // k (channel) chunk depth

// Device scratch (no allocations allowed)
__device__ float g_codebookT[C_ * KCODES];   // [c][code]  1MB
__device__ float g_cnorm[KCODES];
__device__ int   g_idx[NTOK];
__device__ float g_partial[B_ * C_];         // 8192 block sums

// ---------------------------------------------------------------------------
// K1: transpose codebook -> codebookT[c][k], compute |c_k|^2
// grid: 1024 blocks (one per code), 256 threads (one per channel)
// ---------------------------------------------------------------------------
__global__ void __launch_bounds__(256) prep_kernel(const float* __restrict__ cb) {
    __shared__ float s[256];
    int k = blockIdx.x;
    int c = threadIdx.x;
    float v = cb[k * C_ + c];
    g_codebookT[c * KCODES + k] = v;
    s[c] = v * v;
    __syncthreads();
    #pragma unroll
    for (int stride = 128; stride > 0; stride >>= 1) {
        if (c < stride) s[c] += s[c + stride];
        __syncthreads();
    }
    if (c == 0) g_cnorm[k] = s[0];
}

// ---------------------------------------------------------------------------
// K2: argmin over codes. score = |c|^2 - 2 u.c  (|u|^2 dropped: constant/token)
// grid: 512 blocks of 64 tokens; 256 threads (16x16), 4x4 register tiles.
// ---------------------------------------------------------------------------
__global__ void __launch_bounds__(256, 2) argmin_kernel(const float* __restrict__ u,
                                                        float* __restrict__ out_idx) {
    __shared__ float As[CK][BT];      // 8KB  u chunk   [k][token]
    __shared__ float Bs[CK][KT];      // 8KB  code chunk[k][code]
    __shared__ float rv[BT][17];      // final cross-thread reduction (padded)
    __shared__ int   ri[BT][17];

    const int tid = threadIdx.x;
    const int tx = tid & 15;          // code quad
    const int ty = tid >> 4;          // token quad

    const int t0  = blockIdx.x * BT;
    const int b   = t0 >> 10;
    const int hw0 = t0 & 1023;
    const float* ub = u + ((long)b * C_) * HW_ + hw0;

    float best[4] = {3.4e38f, 3.4e38f, 3.4e38f, 3.4e38f};
    int   bidx[4] = {0, 0, 0, 0};

    for (int kt = 0; kt < KCODES / KT; ++kt) {
        const int code0 = kt * KT;
        float acc[4][4];
        #pragma unroll
        for (int i = 0; i < 4; ++i)
            #pragma unroll
            for (int j = 0; j < 4; ++j) acc[i][j] = 0.f;

        for (int kc = 0; kc < C_ / CK; ++kc) {
            const int k0 = kc * CK;
            // load As: 64 tok x 32 k = 512 float4, 2 per thread
            #pragma unroll
            for (int p = 0; p < 2; ++p) {
                int f = tid + p * 256;
                int row = f >> 4, col = (f & 15) << 2;
                *(float4*)&As[row][col] =
                    *(const float4*)&ub[(long)(k0 + row) * HW_ + col];
            }
            // load Bs from transposed codebook (coalesced)
            #pragma unroll
            for (int p = 0; p < 2; ++p) {
                int f = tid + p * 256;
                int row = f >> 4, col = (f & 15) << 2;
                *(float4*)&Bs[row][col] =
                    *(const float4*)&g_codebookT[(k0 + row) * KCODES + code0 + col];
            }
            __syncthreads();
            #pragma unroll
            for (int kk = 0; kk < CK; ++kk) {
                float4 a = *(float4*)&As[kk][ty << 2];
                float4 v = *(float4*)&Bs[kk][tx << 2];
                acc[0][0] = fmaf(a.x, v.x, acc[0][0]);
                acc[0][1] = fmaf(a.x, v.y, acc[0][1]);
                acc[0][2] = fmaf(a.x, v.z, acc[0][2]);
                acc[0][3] = fmaf(a.x, v.w, acc[0][3]);
                acc[1][0] = fmaf(a.y, v.x, acc[1][0]);
                acc[1][1] = fmaf(a.y, v.y, acc[1][1]);
                acc[1][2] = fmaf(a.y, v.z, acc[1][2]);
                acc[1][3] = fmaf(a.y, v.w, acc[1][3]);
                acc[2][0] = fmaf(a.z, v.x, acc[2][0]);
                acc[2][1] = fmaf(a.z, v.y, acc[2][1]);
                acc[2][2] = fmaf(a.z, v.z, acc[2][2]);
                acc[2][3] = fmaf(a.z, v.w, acc[2][3]);
                acc[3][0] = fmaf(a.w, v.x, acc[3][0]);
                acc[3][1] = fmaf(a.w, v.y, acc[3][1]);
                acc[3][2] = fmaf(a.w, v.z, acc[3][2]);
                acc[3][3] = fmaf(a.w, v.w, acc[3][3]);
            }
            __syncthreads();
        }
        // fold this code tile into running argmin
        #pragma unroll
        for (int j = 0; j < 4; ++j) {
            int code = code0 + (tx << 2) + j;
            float cn = __ldg(&g_cnorm[code]);
            #pragma unroll
            for (int i = 0; i < 4; ++i) {
                float s = fmaf(-2.f, acc[i][j], cn);
                if (s < best[i]) { best[i] = s; bidx[i] = code; }
            }
        }
    }

    #pragma unroll
    for (int i = 0; i < 4; ++i) {
        rv[(ty << 2) + i][tx] = best[i];
        ri[(ty << 2) + i][tx] = bidx[i];
    }
    __syncthreads();
    if (tid < BT) {
        float bv = rv[tid][0];
        int bi = ri[tid][0];
        #pragma unroll
        for (int x = 1; x < 16; ++x) {
            float v = rv[tid][x];
            int ix = ri[tid][x];
            if (v < bv || (v == bv && ix < bi)) { bv = v; bi = ix; }
        }
        g_idx[t0 + tid] = bi;
        out_idx[t0 + tid] = (float)bi;
    }
}

// ---------------------------------------------------------------------------
// K3: epilogue. For each (b, c): copy u, gather z_q = codebookT[c][idx],
// write z_train (= z_q since u - stop_grad(u) == 0 numerically),
// accumulate (z_q - u)^2 deterministically per block.
// grid: (256, 32), 256 threads.
// ---------------------------------------------------------------------------
__global__ void __launch_bounds__(256) epilogue_kernel(const float* __restrict__ u,
                                                       float* __restrict__ out) {
    __shared__ float col[KCODES];
    __shared__ float sred[256];
    const int c = blockIdx.x;
    const int b = blockIdx.y;
    const int tid = threadIdx.x;

    ((float4*)col)[tid] = ((const float4*)(g_codebookT + c * KCODES))[tid];
    __syncthreads();

    const long base = ((long)(b * C_ + c)) << 10;   // *1024
    const float* ub = u + base;
    float* ou = out + OFF_U + base;
    float* oz = out + OFF_ZT + base;
    const int* ib = g_idx + (b << 10);

    float acc = 0.f;
    #pragma unroll
    for (int j = 0; j < 4; ++j) {
        int hw = tid + (j << 8);
        int i = ib[hw];
        float z = col[i];
        float uu = ub[hw];
        ou[hw] = uu;
        oz[hw] = z;
        float d = z - uu;
        acc = fmaf(d, d, acc);
    }
    sred[tid] = acc;
    __syncthreads();
    #pragma unroll
    for (int stride = 128; stride > 0; stride >>= 1) {
        if (tid < stride) sred[tid] += sred[tid + stride];
        __syncthreads();
    }
    if (tid == 0) g_partial[b * C_ + c] = sred[0];
}

// ---------------------------------------------------------------------------
// K4: final deterministic loss reduce. vq = (1 + BETA) * mean((z_q - u)^2)
// (codebook and commitment losses are identical expressions numerically)
// ---------------------------------------------------------------------------
__global__ void __launch_bounds__(256) loss_kernel(float* __restrict__ out) {
    __shared__ float s[256];
    const int tid = threadIdx.x;
    float a = 0.f;
    for (int i = tid; i < B_ * C_; i += 256) a += g_partial[i];
    s[tid] = a;
    __syncthreads();
    #pragma unroll
    for (int stride = 128; stride > 0; stride >>= 1) {
        if (tid < stride) s[tid] += s[tid + stride];
        __syncthreads();
    }
    if (tid == 0)
        out[OFF_LOSS] = s[0] * (1.0f + BETA) / (float)SZ_U;
}

// ---------------------------------------------------------------------------
extern "C" void kernel_launch(void* const* d_in, const int* in_sizes, int n_in,
                              void* d_out, int out_size) {
    const float* u  = (const float*)d_in[0];
    const float* cb = (const float*)d_in[1];
    float* out = (float*)d_out;

    prep_kernel<<<KCODES, 256>>>(cb);
    argmin_kernel<<<NTOK / BT, 256>>>(u, out + OFF_IDX);
    epilogue_kernel<<<dim3(C_, B_), 256>>>(u, out);
    loss_kernel<<<1, 256>>>(out);
}

// round 3
// speedup vs baseline: 1.0395x; 1.0395x over previous
#include <cuda_runtime.h>
#include <cuda_bf16.h>
#include <cstdint>

// Problem constants
#define B_      32
#define C_      256
#define HW_     1024
#define NTOK    32768
#define KCODES  1024
#define BETA    0.25f

// Output layout (concatenated float32): u, z_train, vq_loss, indices
#define SZ_U    8388608
#define OFF_U   0
#define OFF_ZT  8388608
#define OFF_LOSS 16777216
#define OFF_IDX  16777217

// GEMM tiling
#define TOKT 256        // tokens per block
#define CODT 64         // codes per block
#define SA   264        // A smem stride (floats): %32 == 8 -> conflict-free frags
#define SB   36         // B smem stride (floats): %32 == 4 -> conflict-free frags

// Device scratch (static; no runtime allocation allowed)
__device__ float g_codebookT[C_ * KCODES];     // [c][code] for epilogue gather
__device__ float g_cnorm[KCODES];
__device__ float g_cmax;                       // max ||c||
__device__ float g_unorm[NTOK];                // ||u_tok||
__device__ int   g_idx[NTOK];
__device__ float g_partial[B_ * C_];
__device__ float g_S[(size_t)KCODES * NTOK];   // [code][token] tf32 scores, 128 MB

// ---------------------------------------------------------------------------
__device__ __forceinline__ uint32_t to_tf32(float f) {
    uint32_t r;
    asm("cvt.rna.tf32.f32 %0, %1;" : "=r"(r) : "f"(f));
    return r;
}

__device__ __forceinline__ void mma_tf32(float* c, const uint32_t* a,
                                         const uint32_t* b) {
    asm volatile(
        "mma.sync.aligned.m16n8k8.row.col.f32.tf32.tf32.f32 "
        "{%0,%1,%2,%3}, {%4,%5,%6,%7}, {%8,%9}, {%0,%1,%2,%3};"
        : "+f"(c[0]), "+f"(c[1]), "+f"(c[2]), "+f"(c[3])
        : "r"(a[0]), "r"(a[1]), "r"(a[2]), "r"(a[3]), "r"(b[0]), "r"(b[1]));
}

// ---------------------------------------------------------------------------
// K0: codebook prep: transpose to [c][code] + |c|^2
// ---------------------------------------------------------------------------
__global__ void __launch_bounds__(256) prep_kernel(const float* __restrict__ cb) {
    __shared__ float s[256];
    int k = blockIdx.x;
    int c = threadIdx.x;
    float v = cb[k * C_ + c];
    g_codebookT[c * KCODES + k] = v;
    s[c] = v * v;
    __syncthreads();
    #pragma unroll
    for (int stride = 128; stride > 0; stride >>= 1) {
        if (c < stride) s[c] += s[c + stride];
        __syncthreads();
    }
    if (c == 0) g_cnorm[k] = s[0];
}

// K0b: g_cmax = max ||c||  (1 block, 256 threads)
__global__ void __launch_bounds__(256) cmax_kernel() {
    __shared__ float s[256];
    int tid = threadIdx.x;
    float m = 0.f;
    for (int i = tid; i < KCODES; i += 256) m = fmaxf(m, g_cnorm[i]);
    s[tid] = m;
    __syncthreads();
    #pragma unroll
    for (int stride = 128; stride > 0; stride >>= 1) {
        if (tid < stride) s[tid] = fmaxf(s[tid], s[tid + stride]);
        __syncthreads();
    }
    if (tid == 0) g_cmax = sqrtf(s[0]) * 1.0002f;
}

// K0c: per-token ||u||  grid (8 hw-chunks, 32 b), 128 threads
__global__ void __launch_bounds__(128) unorm_kernel(const float* __restrict__ u) {
    const int b = blockIdx.y;
    const int hw = blockIdx.x * 128 + threadIdx.x;
    const float* up = u + (size_t)b * (C_ * HW_) + hw;
    float acc = 0.f;
    #pragma unroll 8
    for (int c = 0; c < C_; ++c) {
        float v = up[c * HW_];
        acc = fmaf(v, v, acc);
    }
    g_unorm[(b << 10) + hw] = sqrtf(acc) * 1.0002f;
}

// ---------------------------------------------------------------------------
// K1: tf32 tensor GEMM: S[code][tok] = cnorm[code] - 2 * (u_tok . c_code)_tf32
// grid (16 code-tiles, 128 token-tiles), 256 threads (8 warps)
// warp w handles tokens [w*32, w*32+32) x all 64 codes; K = 256 in 8 chunks.
// ---------------------------------------------------------------------------
__global__ void __launch_bounds__(256) gemm_kernel(const float* __restrict__ u,
                                                   const float* __restrict__ cb) {
    __shared__ float As[32 * SA];   // [k][tok]  33 KB
    __shared__ float Bs[CODT * SB]; // [code][k]  9 KB

    const int tid = threadIdx.x;
    const int w = tid >> 5, lane = tid & 31;
    const int g = lane >> 2, q = lane & 3;
    const int code0 = blockIdx.x * CODT;
    const int tok0 = blockIdx.y * TOKT;
    const int b = tok0 >> 10, hw0 = tok0 & 1023;
    const float* ub = u + (size_t)b * (C_ * HW_) + hw0;

    float acc[2][8][4];
    #pragma unroll
    for (int m = 0; m < 2; ++m)
        #pragma unroll
        for (int j = 0; j < 8; ++j)
            #pragma unroll
            for (int e = 0; e < 4; ++e) acc[m][j][e] = 0.f;

    const uint32_t* Au = (const uint32_t*)As;
    const uint32_t* Bu = (const uint32_t*)Bs;

    for (int kc = 0; kc < 8; ++kc) {
        const int k0 = kc * 32;
        // stage A: 32 k-rows x 256 tokens, cvt to tf32. 2048 f4, 8/thread
        #pragma unroll
        for (int p = 0; p < 8; ++p) {
            int f = tid + p * 256;
            int kr = f >> 6, t4 = (f & 63) << 2;
            float4 v = *(const float4*)&ub[(size_t)(k0 + kr) * HW_ + t4];
            v.x = __uint_as_float(to_tf32(v.x));
            v.y = __uint_as_float(to_tf32(v.y));
            v.z = __uint_as_float(to_tf32(v.z));
            v.w = __uint_as_float(to_tf32(v.w));
            *(float4*)&As[kr * SA + t4] = v;
        }
        // stage B: 64 codes x 32 k. 512 f4, 2/thread
        #pragma unroll
        for (int p = 0; p < 2; ++p) {
            int f = tid + p * 256;
            int cr = f >> 3, k4 = (f & 7) << 2;
            float4 v = *(const float4*)&cb[(size_t)(code0 + cr) * C_ + k0 + k4];
            v.x = __uint_as_float(to_tf32(v.x));
            v.y = __uint_as_float(to_tf32(v.y));
            v.z = __uint_as_float(to_tf32(v.z));
            v.w = __uint_as_float(to_tf32(v.w));
            *(float4*)&Bs[cr * SB + k4] = v;
        }
        __syncthreads();

        #pragma unroll
        for (int ks = 0; ks < 4; ++ks) {
            const int kb = ks * 8;
            uint32_t bf[8][2];
            #pragma unroll
            for (int j = 0; j < 8; ++j) {
                int row = (j * 8 + g) * SB + kb + q;
                bf[j][0] = Bu[row];
                bf[j][1] = Bu[row + 4];
            }
            #pragma unroll
            for (int m = 0; m < 2; ++m) {
                const int arow = w * 32 + m * 16 + g;
                uint32_t af[4];
                af[0] = Au[(kb + q) * SA + arow];
                af[1] = Au[(kb + q) * SA + arow + 8];
                af[2] = Au[(kb + q + 4) * SA + arow];
                af[3] = Au[(kb + q + 4) * SA + arow + 8];
                #pragma unroll
                for (int j = 0; j < 8; ++j) mma_tf32(acc[m][j], af, bf[j]);
            }
        }
        __syncthreads();
    }

    // epilogue: score = cnorm - 2*dot, write S[code][tok]
    #pragma unroll
    for (int m = 0; m < 2; ++m) {
        const int t_lo = tok0 + w * 32 + m * 16 + g;
        #pragma unroll
        for (int j = 0; j < 8; ++j) {
            const int col = code0 + j * 8 + q * 2;
            const float cn0 = __ldg(&g_cnorm[col]);
            const float cn1 = __ldg(&g_cnorm[col + 1]);
            g_S[(size_t)col * NTOK + t_lo]           = fmaf(-2.f, acc[m][j][0], cn0);
            g_S[(size_t)(col + 1) * NTOK + t_lo]     = fmaf(-2.f, acc[m][j][1], cn1);
            g_S[(size_t)col * NTOK + t_lo + 8]       = fmaf(-2.f, acc[m][j][2], cn0);
            g_S[(size_t)(col + 1) * NTOK + t_lo + 8] = fmaf(-2.f, acc[m][j][3], cn1);
        }
    }
}

// ---------------------------------------------------------------------------
// K2: scan + rescue. thread per token. min1/min2 over tf32 scores; if the gap
// is within the rigorous tf32 error margin, recompute candidates in exact fp32.
// ---------------------------------------------------------------------------
__global__ void __launch_bounds__(256) scan_kernel(const float* __restrict__ u,
                                                   const float* __restrict__ cb,
                                                   float* __restrict__ out_idx) {
    const int tok = blockIdx.x * 256 + threadIdx.x;
    float m1 = 3.4e38f, m2 = 3.4e38f;
    int i1 = 0;
    #pragma unroll 4
    for (int c = 0; c < KCODES; ++c) {
        float s = g_S[(size_t)c * NTOK + tok];
        if (s < m1) { m2 = m1; m1 = s; i1 = c; }
        else if (s < m2) { m2 = s; }
    }
    // rigorous pair margin: 2 * 2^-10 * ||u|| * cmax  (+ accum slack)
    const float margin = g_unorm[tok] * g_cmax * (1.02f / 512.f) + 2e-3f;
    int idx = i1;
    if (m2 - m1 <= margin) {
        const float lim = m1 + margin;
        int cands[24];
        int nc = 0;
        for (int c = 0; c < KCODES; ++c) {
            float s = g_S[(size_t)c * NTOK + tok];
            if (s <= lim) { if (nc < 24) cands[nc] = c; ++nc; }
        }
        const int b = tok >> 10, hw = tok & 1023;
        const float* up = u + (size_t)b * (C_ * HW_) + hw;
        float bd = 3.4e38f;
        if (nc <= 24) {
            for (int ci = 0; ci < nc; ++ci) {
                const int c = cands[ci];
                const float* cp = cb + (size_t)c * C_;
                float dot = 0.f;
                #pragma unroll 8
                for (int k = 0; k < C_; ++k)
                    dot = fmaf(up[(size_t)k * HW_], cp[k], dot);
                float d = fmaf(-2.f, dot, g_cnorm[c]);
                if (d < bd) { bd = d; idx = c; }   // ascending c: ties keep lowest
            }
        } else {
            for (int c = 0; c < KCODES; ++c) {
                const float* cp = cb + (size_t)c * C_;
                float dot = 0.f;
                #pragma unroll 8
                for (int k = 0; k < C_; ++k)
                    dot = fmaf(up[(size_t)k * HW_], cp[k], dot);
                float d = fmaf(-2.f, dot, g_cnorm[c]);
                if (d < bd) { bd = d; idx = c; }
            }
        }
    }
    g_idx[tok] = idx;
    out_idx[tok] = (float)idx;
}

// ---------------------------------------------------------------------------
// K3: outputs. copy u, gather z_q, accumulate (z_q - u)^2 per (b,c)
// ---------------------------------------------------------------------------
__global__ void __launch_bounds__(256) epilogue_kernel(const float* __restrict__ u,
                                                       float* __restrict__ out) {
    __shared__ float col[KCODES];
    __shared__ float sred[256];
    const int c = blockIdx.x;
    const int b = blockIdx.y;
    const int tid = threadIdx.x;

    ((float4*)col)[tid] = ((const float4*)(g_codebookT + c * KCODES))[tid];
    __syncthreads();

    const long base = ((long)(b * C_ + c)) << 10;
    const float* ub = u + base;
    float* ou = out + OFF_U + base;
    float* oz = out + OFF_ZT + base;
    const int* ib = g_idx + (b << 10);

    float acc = 0.f;
    #pragma unroll
    for (int j = 0; j < 4; ++j) {
        int hw = tid + (j << 8);
        int i = ib[hw];
        float z = col[i];
        float uu = ub[hw];
        ou[hw] = uu;
        oz[hw] = z;
        float d = z - uu;
        acc = fmaf(d, d, acc);
    }
    sred[tid] = acc;
    __syncthreads();
    #pragma unroll
    for (int stride = 128; stride > 0; stride >>= 1) {
        if (tid < stride) sred[tid] += sred[tid + stride];
        __syncthreads();
    }
    if (tid == 0) g_partial[b * C_ + c] = sred[0];
}

// ---------------------------------------------------------------------------
// K4: final loss. vq = (1 + BETA) * mean((z_q - u)^2)
// ---------------------------------------------------------------------------
__global__ void __launch_bounds__(256) loss_kernel(float* __restrict__ out) {
    __shared__ float s[256];
    const int tid = threadIdx.x;
    float a = 0.f;
    for (int i = tid; i < B_ * C_; i += 256) a += g_partial[i];
    s[tid] = a;
    __syncthreads();
    #pragma unroll
    for (int stride = 128; stride > 0; stride >>= 1) {
        if (tid < stride) s[tid] += s[tid + stride];
        __syncthreads();
    }
    if (tid == 0)
        out[OFF_LOSS] = s[0] * (1.0f + BETA) / (float)SZ_U;
}

// ---------------------------------------------------------------------------
extern "C" void kernel_launch(void* const* d_in, const int* in_sizes, int n_in,
                              void* d_out, int out_size) {
    const float* u  = (const float*)d_in[0];
    const float* cb = (const float*)d_in[1];
    float* out = (float*)d_out;

    prep_kernel<<<KCODES, 256>>>(cb);
    cmax_kernel<<<1, 256>>>();
    unorm_kernel<<<dim3(8, B_), 128>>>(u);
    gemm_kernel<<<dim3(KCODES / CODT, NTOK / TOKT), 256>>>(u, cb);
    scan_kernel<<<NTOK / 256, 256>>>(u, cb, out + OFF_IDX);
    epilogue_kernel<<<dim3(C_, B_), 256>>>(u, out);
    loss_kernel<<<1, 256>>>(out);
}